// round 13
// baseline (speedup 1.0000x reference)
#include <cuda_runtime.h>
#include <cuda_fp16.h>
#include <math.h>
#include <stdint.h>

#define N_INPUTS   32768
#define N_CODES    8192
#define DIM        512

#define TM       128
#define TN       128
#define KC       64
#define NSEG     4                    // N split into 4 segments of 2048
#define NT_SEG   16                   // N-tiles per segment
#define TOTAL    (NT_SEG * 8)         // 128 chunks per job
#define NTHREADS 512
#define NBLK     (N_INPUTS / TM)      // 256 row-blocks
#define CHUNK_HALFS 8192              // 128 rows x 64 cols
#define CHUNK_BYTES 16384
#define NSTAGE   3

// ---------------- device scratch (tiled + swizzled layouts) ----------------
__device__ __half g_xhi[(size_t)N_INPUTS * DIM];
__device__ __half g_xlo[(size_t)N_INPUTS * DIM];
__device__ __half g_whi[(size_t)N_CODES * DIM];
__device__ __half g_wlo[(size_t)N_CODES * DIM];
__device__ float  g_xnorm[N_INPUTS];
__device__ float  g_wnorm[N_CODES];
__device__ float  g_pm[NSEG][N_INPUTS];
__device__ float  g_ps[NSEG][N_INPUTS];
__device__ int    g_pi[NSEG][N_INPUTS];
__device__ float  g_minv[N_INPUTS];
__device__ float  g_rsum[N_INPUTS];
__device__ int    g_argmin[N_INPUTS];
__device__ int    g_counts[N_CODES];
__device__ double g_mse;

// ---------------- SMEM layout (bytes) ----------------
#define OFF_AH   0
#define OFF_AL   16384
#define OFF_BH   32768
#define OFF_BL   49152
#define STAGE_SZ 65536
#define OFF_RM   196608      // float[128][4]
#define OFF_RS   198656      // float[128][4]
#define OFF_RI   200704      // int  [128][4]
#define OFF_BAR  202752      // 3 mbarriers
#define SMEM_TOTAL 202880

// ---------------- helpers ----------------
__device__ __forceinline__ uint32_t smem_u32(const void* p) {
    uint32_t a;
    asm("{ .reg .u64 t; cvta.to.shared.u64 t, %1; cvt.u32.u64 %0, t; }" : "=r"(a) : "l"(p));
    return a;
}
__device__ __forceinline__ void ldsm4(uint32_t* r, uint32_t a) {
    asm volatile("ldmatrix.sync.aligned.m8n8.x4.shared.b16 {%0,%1,%2,%3}, [%4];"
                 : "=r"(r[0]), "=r"(r[1]), "=r"(r[2]), "=r"(r[3]) : "r"(a));
}
__device__ __forceinline__ void mma16816(float* c, const uint32_t* a, uint32_t b0, uint32_t b1) {
    asm volatile("mma.sync.aligned.m16n8k16.row.col.f32.f16.f16.f32 "
                 "{%0,%1,%2,%3}, {%4,%5,%6,%7}, {%8,%9}, {%0,%1,%2,%3};"
                 : "+f"(c[0]), "+f"(c[1]), "+f"(c[2]), "+f"(c[3])
                 : "r"(a[0]), "r"(a[1]), "r"(a[2]), "r"(a[3]), "r"(b0), "r"(b1));
}
__device__ __forceinline__ void mbar_init(uint32_t mbar, uint32_t count) {
    asm volatile("mbarrier.init.shared.b64 [%0], %1;" :: "r"(mbar), "r"(count) : "memory");
}
__device__ __forceinline__ void mbar_expect(uint32_t mbar, uint32_t tx) {
    asm volatile("mbarrier.arrive.expect_tx.shared.b64 _, [%0], %1;" :: "r"(mbar), "r"(tx) : "memory");
}
__device__ __forceinline__ void mbar_wait(uint32_t mbar, uint32_t parity) {
    asm volatile(
        "{\n\t.reg .pred P;\n\t"
        "WL_%=:\n\t"
        "mbarrier.try_wait.parity.acquire.cta.shared::cta.b64 P, [%0], %1, 0x989680;\n\t"
        "@P bra.uni WD_%=;\n\t"
        "bra.uni WL_%=;\n\t"
        "WD_%=:\n\t}"
        :: "r"(mbar), "r"(parity) : "memory");
}
__device__ __forceinline__ void bulk_cp(uint32_t dst, const void* src, uint32_t bytes, uint32_t mbar) {
    asm volatile("cp.async.bulk.shared::cluster.global.mbarrier::complete_tx::bytes [%0], [%1], %2, [%3];"
                 :: "r"(dst), "l"(__cvta_generic_to_global(src)), "r"(bytes), "r"(mbar) : "memory");
}
__device__ __forceinline__ void stg_cs_v2(float* p, float a, float b) {
    asm volatile("st.global.cs.v2.f32 [%0], {%1, %2};" :: "l"(p), "f"(a), "f"(b) : "memory");
}

// ---------------- small kernels ----------------
__global__ void init_kernel() {
    int i = blockIdx.x * blockDim.x + threadIdx.x;
    if (i < N_CODES) g_counts[i] = 0;
    if (i == 0) g_mse = 0.0;
}

// convert fp32 -> split fp16 hi/lo, writing the tiled+swizzled chunk layout
__global__ void convert_kernel(const float* __restrict__ X, const float* __restrict__ W) {
    const size_t NXG = (size_t)N_INPUTS * 64;   // 16B-groups in X
    const size_t NWG = (size_t)N_CODES * 64;
    size_t idx = (size_t)blockIdx.x * blockDim.x + threadIdx.x;
    if (idx >= NXG + NWG) return;
    const float* src; __half *hdst, *ldst; size_t r; int g;
    if (idx < NXG) { src = X; hdst = g_xhi; ldst = g_xlo; r = idx >> 6; g = (int)(idx & 63); }
    else { idx -= NXG; src = W; hdst = g_whi; ldst = g_wlo; r = idx >> 6; g = (int)(idx & 63); }

    float4 v0 = *(const float4*)(src + r * DIM + g * 8);
    float4 v1 = *(const float4*)(src + r * DIM + g * 8 + 4);
    __half h[8], l[8];
    float f[8] = {v0.x, v0.y, v0.z, v0.w, v1.x, v1.y, v1.z, v1.w};
    #pragma unroll
    for (int i = 0; i < 8; i++) {
        h[i] = __float2half(f[i]);
        l[i] = __float2half(f[i] - __half2float(h[i]));
    }
    const int rb = (int)(r >> 7), rl = (int)(r & 127);
    const int kc = g >> 3, gin = g & 7;
    const size_t dst = ((size_t)(rb * 8 + kc) * 128 + rl) * 64 + (size_t)((gin ^ (rl & 7)) * 8);
    *(uint4*)(hdst + dst) = *(uint4*)h;
    *(uint4*)(ldst + dst) = *(uint4*)l;
}

__global__ void row_norm_kernel(const float* __restrict__ src, float* __restrict__ dst, int rows) {
    int warp = (blockIdx.x * blockDim.x + threadIdx.x) >> 5;
    int lane = threadIdx.x & 31;
    if (warp >= rows) return;
    const float4* p = (const float4*)(src + (size_t)warp * DIM);
    float s = 0.f;
    #pragma unroll
    for (int i = lane; i < DIM / 4; i += 32) {
        float4 v = p[i];
        s += v.x * v.x + v.y * v.y + v.z * v.z + v.w * v.w;
    }
    #pragma unroll
    for (int o = 16; o; o >>= 1) s += __shfl_xor_sync(0xffffffffu, s, o);
    if (lane == 0) dst[warp] = s;
}

// ---------------- main HMMA distance kernel (3-stage pipeline) ----------------
__global__ void __launch_bounds__(NTHREADS, 1)
dist_kernel(float* __restrict__ probs) {
    extern __shared__ __align__(1024) char smem[];
    const int tid  = threadIdx.x;
    const int mb   = blockIdx.x & (NBLK - 1);      // row-block
    const int nseg = blockIdx.x >> 8;              // N segment (0..3)
    const int m0   = mb * TM;
    const int tbase = nseg * NT_SEG;               // absolute first N-tile
    const int warp = tid >> 5, lane = tid & 31;
    const int wm = warp >> 2, wn = warp & 3;       // 4 x 4 warp grid, 32x32 warp tiles
    const int lr = lane >> 2, lc = lane & 3;
    const uint32_t sbase = smem_u32(smem);

    if (tid == 0) {
        mbar_init(sbase + OFF_BAR, 1);
        mbar_init(sbase + OFF_BAR + 8, 1);
        mbar_init(sbase + OFF_BAR + 16, 1);
    }
    __syncthreads();

    // ---- ldmatrix per-thread constants ----
    const uint32_t aofs = (uint32_t)((wm * 32 + (lane & 15)) << 7);
    const uint32_t bofs = (uint32_t)((wn * 32 + (lane & 15)) << 7);
    const int gsel = lane >> 4, gsw = lane & 7;

    float acc[2][4][4];
    #pragma unroll
    for (int a = 0; a < 2; a++)
        #pragma unroll
        for (int b = 0; b < 4; b++)
            #pragma unroll
            for (int c = 0; c < 4; c++) acc[a][b][c] = 0.f;

    float stm[4], sts[4];
    int   sti[4];
    float xnr[4];
    #pragma unroll
    for (int i = 0; i < 4; i++) {
        stm[i] = 3.0e38f; sts[i] = 0.f; sti[i] = 0;
        xnr[i] = g_xnorm[m0 + wm * 32 + (i >> 1) * 16 + lr + (i & 1) * 8];
    }

    // ---- prologue: bulk-load chunks 0 and 1 ----
    if (tid == 0) {
        #pragma unroll
        for (int p = 0; p < 2; p++) {
            const uint32_t bar = sbase + OFF_BAR + p * 8;
            const uint32_t st  = sbase + (uint32_t)p * STAGE_SZ;
            const size_t ac = (size_t)(mb * 8 + (p & 7)) * CHUNK_HALFS;
            const size_t bc = (size_t)((tbase + (p >> 3)) * 8 + (p & 7)) * CHUNK_HALFS;
            mbar_expect(bar, 4 * CHUNK_BYTES);
            bulk_cp(st + OFF_AH, g_xhi + ac, CHUNK_BYTES, bar);
            bulk_cp(st + OFF_AL, g_xlo + ac, CHUNK_BYTES, bar);
            bulk_cp(st + OFF_BH, g_whi + bc, CHUNK_BYTES, bar);
            bulk_cp(st + OFF_BL, g_wlo + bc, CHUNK_BYTES, bar);
        }
    }

    int stage = 0, par = 0;     // stage and parity for chunk g
    for (int g = 0; g < TOTAL; g++) {
        // ---- issue bulk loads for chunk g+2 (its stage freed by syncthreads after g-1) ----
        if (g + 2 < TOTAL && tid == 0) {
            const int gn = g + 2;
            const int sn = (gn >= 3 * (gn / 3) + 0) ? gn % 3 : 0;  // gn % 3
            const int kc1 = gn & 7, nt1 = gn >> 3;
            const uint32_t st = sbase + (uint32_t)(gn % 3) * STAGE_SZ;
            const uint32_t bar = sbase + OFF_BAR + (gn % 3) * 8;
            (void)sn;
            const size_t ac = (size_t)(mb * 8 + kc1) * CHUNK_HALFS;
            const size_t bc = (size_t)((tbase + nt1) * 8 + kc1) * CHUNK_HALFS;
            mbar_expect(bar, 4 * CHUNK_BYTES);
            bulk_cp(st + OFF_AH, g_xhi + ac, CHUNK_BYTES, bar);
            bulk_cp(st + OFF_AL, g_xlo + ac, CHUNK_BYTES, bar);
            bulk_cp(st + OFF_BH, g_whi + bc, CHUNK_BYTES, bar);
            bulk_cp(st + OFF_BL, g_wlo + bc, CHUNK_BYTES, bar);
        }
        mbar_wait(sbase + OFF_BAR + stage * 8, par);

        // ---- compute chunk g ----
        {
            const uint32_t st = sbase + (uint32_t)stage * STAGE_SZ;
            #pragma unroll
            for (int ks = 0; ks < 4; ks++) {
                const uint32_t gx = (uint32_t)((((ks << 1) | gsel) ^ gsw) << 4);
                uint32_t ah[2][4], bh[2][4], bl[2][4], al[2][4];
                #pragma unroll
                for (int mbk = 0; mbk < 2; mbk++) ldsm4(ah[mbk], st + OFF_AH + aofs + mbk * 2048 + gx);
                #pragma unroll
                for (int nb = 0; nb < 2; nb++) ldsm4(bh[nb], st + OFF_BH + bofs + nb * 2048 + gx);
                #pragma unroll
                for (int mbk = 0; mbk < 2; mbk++)
                    #pragma unroll
                    for (int n8 = 0; n8 < 4; n8++)
                        mma16816(acc[mbk][n8], ah[mbk], bh[n8 >> 1][n8 & 1], bh[n8 >> 1][(n8 & 1) + 2]);
                #pragma unroll
                for (int nb = 0; nb < 2; nb++) ldsm4(bl[nb], st + OFF_BL + bofs + nb * 2048 + gx);
                #pragma unroll
                for (int mbk = 0; mbk < 2; mbk++)
                    #pragma unroll
                    for (int n8 = 0; n8 < 4; n8++)
                        mma16816(acc[mbk][n8], ah[mbk], bl[n8 >> 1][n8 & 1], bl[n8 >> 1][(n8 & 1) + 2]);
                #pragma unroll
                for (int mbk = 0; mbk < 2; mbk++) ldsm4(al[mbk], st + OFF_AL + aofs + mbk * 2048 + gx);
                #pragma unroll
                for (int mbk = 0; mbk < 2; mbk++)
                    #pragma unroll
                    for (int n8 = 0; n8 < 4; n8++)
                        mma16816(acc[mbk][n8], al[mbk], bh[n8 >> 1][n8 & 1], bh[n8 >> 1][(n8 & 1) + 2]);
            }
        }

        // ---- epilogue at end of each N-tile (batched min + single rescale) ----
        if ((g & 7) == 7) {
            const int n0 = (tbase + (g >> 3)) * TN;
            float wns[8];
            #pragma unroll
            for (int nb = 0; nb < 4; nb++) {
                wns[nb * 2]     = __ldg(&g_wnorm[n0 + wn * 32 + nb * 8 + lc * 2]);
                wns[nb * 2 + 1] = __ldg(&g_wnorm[n0 + wn * 32 + nb * 8 + lc * 2 + 1]);
            }
            #pragma unroll
            for (int mbk = 0; mbk < 2; mbk++)
                #pragma unroll
                for (int h = 0; h < 2; h++) {
                    const int i = mbk * 2 + h;
                    const int grow = m0 + wm * 32 + mbk * 16 + lr + h * 8;
                    float d[8];
                    #pragma unroll
                    for (int nb = 0; nb < 4; nb++) {
                        d[nb * 2]     = fmaf(-2.f, acc[mbk][nb][h * 2],     xnr[i] + wns[nb * 2]);
                        d[nb * 2 + 1] = fmaf(-2.f, acc[mbk][nb][h * 2 + 1], xnr[i] + wns[nb * 2 + 1]);
                        acc[mbk][nb][h * 2] = 0.f; acc[mbk][nb][h * 2 + 1] = 0.f;
                    }
                    // stores (streaming)
                    #pragma unroll
                    for (int nb = 0; nb < 4; nb++)
                        stg_cs_v2(probs + (size_t)grow * N_CODES + n0 + wn * 32 + nb * 8 + lc * 2,
                                  d[nb * 2], d[nb * 2 + 1]);
                    // batched min + argmin (ascending j = ascending col)
                    float m8 = d[0]; int j8 = 0;
                    #pragma unroll
                    for (int j = 1; j < 8; j++)
                        if (d[j] < m8) { m8 = d[j]; j8 = j; }
                    float s8 = 0.f;
                    #pragma unroll
                    for (int j = 0; j < 8; j++) s8 += __expf(m8 - d[j]);
                    const int c8 = n0 + wn * 32 + (j8 >> 1) * 8 + lc * 2 + (j8 & 1);
                    // single rescale merge
                    if (m8 < stm[i]) {
                        sts[i] = fmaf(sts[i], __expf(m8 - stm[i]), s8);
                        stm[i] = m8; sti[i] = c8;
                    } else {
                        sts[i] = fmaf(s8, __expf(stm[i] - m8), sts[i]);
                    }
                }
        }
        __syncthreads();
        if (++stage == NSTAGE) { stage = 0; par ^= 1; }
    }

    // ---- final merge: quad lanes -> smem -> per-row over 4 N-warps ----
    float* rm = (float*)(smem + OFF_RM);
    float* rs = (float*)(smem + OFF_RS);
    int*   ri = (int*)  (smem + OFF_RI);
    #pragma unroll
    for (int i = 0; i < 4; i++) {
        float m = stm[i], s = sts[i];
        int   ix = sti[i];
        #pragma unroll
        for (int o = 1; o <= 2; o <<= 1) {
            float om = __shfl_xor_sync(0xffffffffu, m, o);
            float os = __shfl_xor_sync(0xffffffffu, s, o);
            int   oi = __shfl_xor_sync(0xffffffffu, ix, o);
            float nm = fminf(m, om);
            s = s * __expf(nm - m) + os * __expf(nm - om);
            if (om < m || (om == m && oi < ix)) ix = oi;
            m = nm;
        }
        if (lc == 0) {
            const int rowl = wm * 32 + (i >> 1) * 16 + lr + (i & 1) * 8;
            rm[rowl * 4 + wn] = m;
            rs[rowl * 4 + wn] = s;
            ri[rowl * 4 + wn] = ix;
        }
    }
    __syncthreads();
    if (tid < TM) {
        float m = rm[tid * 4], s = rs[tid * 4];
        int   ix = ri[tid * 4];
        #pragma unroll
        for (int w = 1; w < 4; w++) {
            float om = rm[tid * 4 + w], os = rs[tid * 4 + w];
            int   oi = ri[tid * 4 + w];
            float nm = fminf(m, om);
            s = s * __expf(nm - m) + os * __expf(nm - om);
            if (om < m || (om == m && oi < ix)) ix = oi;
            m = nm;
        }
        g_pm[nseg][m0 + tid] = m;
        g_ps[nseg][m0 + tid] = s;
        g_pi[nseg][m0 + tid] = ix;
    }
}

// ---------------- merge the 4 N-segment partials per row ----------------
__global__ void merge_kernel() {
    int i = blockIdx.x * blockDim.x + threadIdx.x;
    if (i >= N_INPUTS) return;
    float m = g_pm[0][i], s = g_ps[0][i];
    int   ix = g_pi[0][i];
    #pragma unroll
    for (int seg = 1; seg < NSEG; seg++) {
        float om = g_pm[seg][i], os = g_ps[seg][i];
        int   oi = g_pi[seg][i];
        float nm = fminf(m, om);
        s = s * __expf(nm - m) + os * __expf(nm - om);
        if (om < m) ix = oi;            // ties keep earlier segment (lower index)
        m = nm;
    }
    g_minv[i]   = m;
    g_rsum[i]   = 1.0f / s;
    g_argmin[i] = ix;
}

// ---------------- quantized_st + histogram + mse ----------------
__global__ void quantize_kernel(const float* __restrict__ X, const float* __restrict__ W,
                                float* __restrict__ qout) {
    int warp = (blockIdx.x * blockDim.x + threadIdx.x) >> 5;
    int lane = threadIdx.x & 31;
    if (warp >= N_INPUTS) return;
    const int idx = g_argmin[warp];
    if (lane == 0) atomicAdd(&g_counts[idx], 1);

    const float4* xp = (const float4*)(X + (size_t)warp * DIM);
    const float4* wp = (const float4*)(W + (size_t)idx * DIM);
    float4*       qp = (float4*)(qout + (size_t)warp * DIM);
    float sq = 0.f;
    #pragma unroll
    for (int i = lane; i < DIM / 4; i += 32) {
        float4 xv = xp[i], wv = wp[i];
        float tx = wv.x - xv.x, ty = wv.y - xv.y, tz = wv.z - xv.z, tw = wv.w - xv.w;
        qp[i] = wv;
        sq += tx * tx + ty * ty + tz * tz + tw * tw;
    }
    #pragma unroll
    for (int o = 16; o; o >>= 1) sq += __shfl_xor_sync(0xffffffffu, sq, o);
    if (lane == 0) atomicAdd(&g_mse, (double)sq);
}

// ---------------- normalize distances -> probs (streaming) ----------------
__global__ void norm_probs_kernel(float* __restrict__ probs) {
    const size_t i4 = (size_t)blockIdx.x * blockDim.x + threadIdx.x;
    const int row = (int)(i4 >> 11);          // 2048 float4 per row
    const float m  = g_minv[row];
    const float rs = g_rsum[row];
    float4 v = __ldcs((const float4*)probs + i4);
    v.x = __expf(m - v.x) * rs;
    v.y = __expf(m - v.y) * rs;
    v.z = __expf(m - v.z) * rs;
    v.w = __expf(m - v.w) * rs;
    __stcs((float4*)probs + i4, v);
}

// ---------------- loss + perplexity ----------------
__global__ void finalize_kernel(float* __restrict__ out_loss, float* __restrict__ out_perp) {
    __shared__ double sh[256];
    const int tid = threadIdx.x;
    double h = 0.0;
    for (int i = tid; i < N_CODES; i += 256) {
        float avg = (float)g_counts[i] / (float)N_INPUTS;
        h -= (double)(avg * logf(avg + 1e-10f));
    }
    sh[tid] = h;
    __syncthreads();
    for (int o = 128; o; o >>= 1) {
        if (tid < o) sh[tid] += sh[tid + o];
        __syncthreads();
    }
    if (tid == 0) {
        *out_perp = expf((float)sh[0]);
        *out_loss = (float)(1.25 * g_mse / (double)((size_t)N_INPUTS * DIM));
    }
}

// ---------------- launch ----------------
extern "C" void kernel_launch(void* const* d_in, const int* in_sizes, int n_in,
                              void* d_out, int out_size) {
    const float* X = (const float*)d_in[0];
    const float* W = (const float*)d_in[1];
    float* out = (float*)d_out;

    float* q_out    = out;
    float* probs    = out + (size_t)N_INPUTS * DIM;
    float* loss_out = probs + (size_t)N_INPUTS * N_CODES;
    float* perp_out = loss_out + 1;

    init_kernel<<<(N_CODES + 255) / 256, 256>>>();

    const size_t ngroups = (size_t)N_INPUTS * 64 + (size_t)N_CODES * 64;
    convert_kernel<<<(unsigned)((ngroups + 255) / 256), 256>>>(X, W);

    float* d_xnorm; cudaGetSymbolAddress((void**)&d_xnorm, g_xnorm);
    float* d_wnorm; cudaGetSymbolAddress((void**)&d_wnorm, g_wnorm);
    row_norm_kernel<<<(N_INPUTS * 32) / 256, 256>>>(X, d_xnorm, N_INPUTS);
    row_norm_kernel<<<(N_CODES  * 32) / 256, 256>>>(W, d_wnorm, N_CODES);

    cudaFuncSetAttribute(dist_kernel, cudaFuncAttributeMaxDynamicSharedMemorySize, SMEM_TOTAL);
    dist_kernel<<<NBLK * NSEG, NTHREADS, SMEM_TOTAL>>>(probs);

    merge_kernel<<<N_INPUTS / 256, 256>>>();

    quantize_kernel<<<(N_INPUTS * 32) / 256, 256>>>(X, W, q_out);

    const size_t n4 = (size_t)N_INPUTS * N_CODES / 4;
    norm_probs_kernel<<<(unsigned)(n4 / 256), 256>>>(probs);

    finalize_kernel<<<1, 256>>>(loss_out, perp_out);
}

// round 16
// speedup vs baseline: 1.4464x; 1.4464x over previous
#include <cuda_runtime.h>
#include <cuda_fp16.h>
#include <math.h>
#include <stdint.h>

#define N_INPUTS   32768
#define N_CODES    8192
#define DIM        512

#define TM       128
#define TN       128
#define KC       64
#define NSEG     4                    // N split into 4 segments of 2048
#define NT_SEG   16                   // N-tiles per segment
#define TOTAL    (NT_SEG * 8)         // 128 chunks per job
#define NTHREADS 512
#define NBLK     (N_INPUTS / TM)      // 256 row-blocks
#define CHUNK_HALFS 8192              // 128 rows x 64 cols
#define CHUNK_BYTES 16384

// ---------------- device scratch (tiled + swizzled layouts) ----------------
__device__ __half g_xhi[(size_t)N_INPUTS * DIM];
__device__ __half g_xlo[(size_t)N_INPUTS * DIM];
__device__ __half g_whi[(size_t)N_CODES * DIM];
__device__ __half g_wlo[(size_t)N_CODES * DIM];
__device__ float  g_xnorm[N_INPUTS];
__device__ float  g_wnorm[N_CODES];
__device__ float  g_pm[NSEG][N_INPUTS];
__device__ float  g_ps[NSEG][N_INPUTS];
__device__ int    g_pi[NSEG][N_INPUTS];
__device__ float  g_minv[N_INPUTS];
__device__ float  g_rsum[N_INPUTS];
__device__ int    g_argmin[N_INPUTS];
__device__ int    g_counts[N_CODES];
__device__ double g_mse;

// ---------------- SMEM layout (bytes) ----------------
#define OFF_AH   0
#define OFF_AL   16384
#define OFF_BH   32768
#define OFF_BL   49152
#define STAGE_SZ 65536
#define OFF_RM   131072      // float[128][4]
#define OFF_RS   133120      // float[128][4]
#define OFF_RI   135168      // int  [128][4]
#define OFF_BAR  137216      // 2 mbarriers
#define SMEM_TOTAL 137344

// ---------------- helpers ----------------
__device__ __forceinline__ uint32_t smem_u32(const void* p) {
    uint32_t a;
    asm("{ .reg .u64 t; cvta.to.shared.u64 t, %1; cvt.u32.u64 %0, t; }" : "=r"(a) : "l"(p));
    return a;
}
__device__ __forceinline__ void ldsm4(uint32_t* r, uint32_t a) {
    asm volatile("ldmatrix.sync.aligned.m8n8.x4.shared.b16 {%0,%1,%2,%3}, [%4];"
                 : "=r"(r[0]), "=r"(r[1]), "=r"(r[2]), "=r"(r[3]) : "r"(a));
}
__device__ __forceinline__ void mma16816(float* c, const uint32_t* a, uint32_t b0, uint32_t b1) {
    asm volatile("mma.sync.aligned.m16n8k16.row.col.f32.f16.f16.f32 "
                 "{%0,%1,%2,%3}, {%4,%5,%6,%7}, {%8,%9}, {%0,%1,%2,%3};"
                 : "+f"(c[0]), "+f"(c[1]), "+f"(c[2]), "+f"(c[3])
                 : "r"(a[0]), "r"(a[1]), "r"(a[2]), "r"(a[3]), "r"(b0), "r"(b1));
}
__device__ __forceinline__ void mbar_init(uint32_t mbar, uint32_t count) {
    asm volatile("mbarrier.init.shared.b64 [%0], %1;" :: "r"(mbar), "r"(count) : "memory");
}
__device__ __forceinline__ void mbar_expect(uint32_t mbar, uint32_t tx) {
    asm volatile("mbarrier.arrive.expect_tx.shared.b64 _, [%0], %1;" :: "r"(mbar), "r"(tx) : "memory");
}
__device__ __forceinline__ void mbar_wait(uint32_t mbar, uint32_t parity) {
    asm volatile(
        "{\n\t.reg .pred P;\n\t"
        "WL_%=:\n\t"
        "mbarrier.try_wait.parity.acquire.cta.shared::cta.b64 P, [%0], %1, 0x989680;\n\t"
        "@P bra.uni WD_%=;\n\t"
        "bra.uni WL_%=;\n\t"
        "WD_%=:\n\t}"
        :: "r"(mbar), "r"(parity) : "memory");
}
__device__ __forceinline__ void bulk_cp(uint32_t dst, const void* src, uint32_t bytes, uint32_t mbar) {
    asm volatile("cp.async.bulk.shared::cluster.global.mbarrier::complete_tx::bytes [%0], [%1], %2, [%3];"
                 :: "r"(dst), "l"(__cvta_generic_to_global(src)), "r"(bytes), "r"(mbar) : "memory");
}

// ---------------- small kernels ----------------
__global__ void init_kernel() {
    int i = blockIdx.x * blockDim.x + threadIdx.x;
    if (i < N_CODES) g_counts[i] = 0;
    if (i == 0) g_mse = 0.0;
}

// convert fp32 -> split fp16 hi/lo, writing the tiled+swizzled chunk layout
__global__ void convert_kernel(const float* __restrict__ X, const float* __restrict__ W) {
    const size_t NXG = (size_t)N_INPUTS * 64;   // 16B-groups in X
    const size_t NWG = (size_t)N_CODES * 64;
    size_t idx = (size_t)blockIdx.x * blockDim.x + threadIdx.x;
    if (idx >= NXG + NWG) return;
    const float* src; __half *hdst, *ldst; size_t r; int g;
    if (idx < NXG) { src = X; hdst = g_xhi; ldst = g_xlo; r = idx >> 6; g = (int)(idx & 63); }
    else { idx -= NXG; src = W; hdst = g_whi; ldst = g_wlo; r = idx >> 6; g = (int)(idx & 63); }

    float4 v0 = *(const float4*)(src + r * DIM + g * 8);
    float4 v1 = *(const float4*)(src + r * DIM + g * 8 + 4);
    __half h[8], l[8];
    float f[8] = {v0.x, v0.y, v0.z, v0.w, v1.x, v1.y, v1.z, v1.w};
    #pragma unroll
    for (int i = 0; i < 8; i++) {
        h[i] = __float2half(f[i]);
        l[i] = __float2half(f[i] - __half2float(h[i]));
    }
    const int rb = (int)(r >> 7), rl = (int)(r & 127);
    const int kc = g >> 3, gin = g & 7;
    const size_t dst = ((size_t)(rb * 8 + kc) * 128 + rl) * 64 + (size_t)((gin ^ (rl & 7)) * 8);
    *(uint4*)(hdst + dst) = *(uint4*)h;
    *(uint4*)(ldst + dst) = *(uint4*)l;
}

__global__ void row_norm_kernel(const float* __restrict__ src, float* __restrict__ dst, int rows) {
    int warp = (blockIdx.x * blockDim.x + threadIdx.x) >> 5;
    int lane = threadIdx.x & 31;
    if (warp >= rows) return;
    const float4* p = (const float4*)(src + (size_t)warp * DIM);
    float s = 0.f;
    #pragma unroll
    for (int i = lane; i < DIM / 4; i += 32) {
        float4 v = p[i];
        s += v.x * v.x + v.y * v.y + v.z * v.z + v.w * v.w;
    }
    #pragma unroll
    for (int o = 16; o; o >>= 1) s += __shfl_xor_sync(0xffffffffu, s, o);
    if (lane == 0) dst[warp] = s;
}

// ---------------- main HMMA distance kernel (1024 jobs: 256 rowblocks x 4 N-segments) ----------------
__global__ void __launch_bounds__(NTHREADS, 1)
dist_kernel(float* __restrict__ probs) {
    extern __shared__ __align__(1024) char smem[];
    const int tid  = threadIdx.x;
    const int mb   = blockIdx.x & (NBLK - 1);      // row-block
    const int nseg = blockIdx.x >> 8;              // N segment (0..3)
    const int m0   = mb * TM;
    const int tbase = nseg * NT_SEG;               // absolute first N-tile
    const int warp = tid >> 5, lane = tid & 31;
    const int wm = warp >> 2, wn = warp & 3;       // 4 x 4 warp grid, 32x32 warp tiles
    const int lr = lane >> 2, lc = lane & 3;
    const uint32_t sbase = smem_u32(smem);
    const uint32_t bar0 = sbase + OFF_BAR, bar1 = sbase + OFF_BAR + 8;

    if (tid == 0) { mbar_init(bar0, 1); mbar_init(bar1, 1); }
    __syncthreads();

    // ---- ldmatrix per-thread constants ----
    const uint32_t aofs = (uint32_t)((wm * 32 + (lane & 15)) << 7);
    const uint32_t bofs = (uint32_t)((wn * 32 + (lane & 15)) << 7);
    const int gsel = lane >> 4, gsw = lane & 7;

    float acc[2][4][4];
    #pragma unroll
    for (int a = 0; a < 2; a++)
        #pragma unroll
        for (int b = 0; b < 4; b++)
            #pragma unroll
            for (int c = 0; c < 4; c++) acc[a][b][c] = 0.f;

    float stm[4], sts[4];
    int   sti[4];
    float xnr[4];
    #pragma unroll
    for (int i = 0; i < 4; i++) {
        stm[i] = 3.0e38f; sts[i] = 0.f; sti[i] = 0;
        xnr[i] = g_xnorm[m0 + wm * 32 + (i >> 1) * 16 + lr + (i & 1) * 8];
    }

    // ---- prologue: bulk-load chunk 0 into stage 0 ----
    if (tid == 0) {
        const size_t ac = (size_t)(mb * 8 + 0) * CHUNK_HALFS;
        const size_t bc = (size_t)(tbase * 8 + 0) * CHUNK_HALFS;
        mbar_expect(bar0, 4 * CHUNK_BYTES);
        bulk_cp(sbase + OFF_AH, g_xhi + ac, CHUNK_BYTES, bar0);
        bulk_cp(sbase + OFF_AL, g_xlo + ac, CHUNK_BYTES, bar0);
        bulk_cp(sbase + OFF_BH, g_whi + bc, CHUNK_BYTES, bar0);
        bulk_cp(sbase + OFF_BL, g_wlo + bc, CHUNK_BYTES, bar0);
    }

    for (int g = 0; g < TOTAL; g++) {
        // ---- issue bulk loads for chunk g+1 ----
        if (g + 1 < TOTAL && tid == 0) {
            const int kc1 = (g + 1) & 7, nt1 = (g + 1) >> 3;
            const uint32_t st = sbase + (uint32_t)((g + 1) & 1) * STAGE_SZ;
            const uint32_t bar = ((g + 1) & 1) ? bar1 : bar0;
            const size_t ac = (size_t)(mb * 8 + kc1) * CHUNK_HALFS;
            const size_t bc = (size_t)((tbase + nt1) * 8 + kc1) * CHUNK_HALFS;
            mbar_expect(bar, 4 * CHUNK_BYTES);
            bulk_cp(st + OFF_AH, g_xhi + ac, CHUNK_BYTES, bar);
            bulk_cp(st + OFF_AL, g_xlo + ac, CHUNK_BYTES, bar);
            bulk_cp(st + OFF_BH, g_whi + bc, CHUNK_BYTES, bar);
            bulk_cp(st + OFF_BL, g_wlo + bc, CHUNK_BYTES, bar);
        }
        mbar_wait((g & 1) ? bar1 : bar0, (g >> 1) & 1);

        // ---- compute chunk g ----
        {
            const uint32_t st = sbase + (uint32_t)(g & 1) * STAGE_SZ;
            #pragma unroll
            for (int ks = 0; ks < 4; ks++) {
                const uint32_t gx = (uint32_t)((((ks << 1) | gsel) ^ gsw) << 4);
                uint32_t ah[2][4], bh[2][4], bl[2][4], al[2][4];
                #pragma unroll
                for (int mbk = 0; mbk < 2; mbk++) ldsm4(ah[mbk], st + OFF_AH + aofs + mbk * 2048 + gx);
                #pragma unroll
                for (int nb = 0; nb < 2; nb++) ldsm4(bh[nb], st + OFF_BH + bofs + nb * 2048 + gx);
                #pragma unroll
                for (int mbk = 0; mbk < 2; mbk++)
                    #pragma unroll
                    for (int n8 = 0; n8 < 4; n8++)
                        mma16816(acc[mbk][n8], ah[mbk], bh[n8 >> 1][n8 & 1], bh[n8 >> 1][(n8 & 1) + 2]);
                #pragma unroll
                for (int nb = 0; nb < 2; nb++) ldsm4(bl[nb], st + OFF_BL + bofs + nb * 2048 + gx);
                #pragma unroll
                for (int mbk = 0; mbk < 2; mbk++)
                    #pragma unroll
                    for (int n8 = 0; n8 < 4; n8++)
                        mma16816(acc[mbk][n8], ah[mbk], bl[n8 >> 1][n8 & 1], bl[n8 >> 1][(n8 & 1) + 2]);
                #pragma unroll
                for (int mbk = 0; mbk < 2; mbk++) ldsm4(al[mbk], st + OFF_AL + aofs + mbk * 2048 + gx);
                #pragma unroll
                for (int mbk = 0; mbk < 2; mbk++)
                    #pragma unroll
                    for (int n8 = 0; n8 < 4; n8++)
                        mma16816(acc[mbk][n8], al[mbk], bh[n8 >> 1][n8 & 1], bh[n8 >> 1][(n8 & 1) + 2]);
            }
        }

        // ---- epilogue at end of each N-tile ----
        if ((g & 7) == 7) {
            const int n0 = (tbase + (g >> 3)) * TN;
            float wns[8];
            #pragma unroll
            for (int nb = 0; nb < 4; nb++) {
                wns[nb * 2]     = __ldg(&g_wnorm[n0 + wn * 32 + nb * 8 + lc * 2]);
                wns[nb * 2 + 1] = __ldg(&g_wnorm[n0 + wn * 32 + nb * 8 + lc * 2 + 1]);
            }
            #pragma unroll
            for (int mbk = 0; mbk < 2; mbk++)
                #pragma unroll
                for (int h = 0; h < 2; h++) {
                    const int i = mbk * 2 + h;
                    const int grow = m0 + wm * 32 + mbk * 16 + lr + h * 8;
                    #pragma unroll
                    for (int nb = 0; nb < 4; nb++) {
                        const int col = n0 + wn * 32 + nb * 8 + lc * 2;
                        float d0 = fmaf(-2.f, acc[mbk][nb][h * 2],     xnr[i] + wns[nb * 2]);
                        float d1 = fmaf(-2.f, acc[mbk][nb][h * 2 + 1], xnr[i] + wns[nb * 2 + 1]);
                        *(float2*)(probs + (size_t)grow * N_CODES + col) = make_float2(d0, d1);
                        if (d0 < stm[i]) { sts[i] = fmaf(sts[i], __expf(d0 - stm[i]), 1.0f); stm[i] = d0; sti[i] = col; }
                        else               sts[i] += __expf(stm[i] - d0);
                        if (d1 < stm[i]) { sts[i] = fmaf(sts[i], __expf(d1 - stm[i]), 1.0f); stm[i] = d1; sti[i] = col + 1; }
                        else               sts[i] += __expf(stm[i] - d1);
                        acc[mbk][nb][h * 2] = 0.f; acc[mbk][nb][h * 2 + 1] = 0.f;
                    }
                }
        }
        __syncthreads();
    }

    // ---- final merge: quad lanes -> smem -> per-row over 4 N-warps ----
    float* rm = (float*)(smem + OFF_RM);
    float* rs = (float*)(smem + OFF_RS);
    int*   ri = (int*)  (smem + OFF_RI);
    #pragma unroll
    for (int i = 0; i < 4; i++) {
        float m = stm[i], s = sts[i];
        int   ix = sti[i];
        #pragma unroll
        for (int o = 1; o <= 2; o <<= 1) {
            float om = __shfl_xor_sync(0xffffffffu, m, o);
            float os = __shfl_xor_sync(0xffffffffu, s, o);
            int   oi = __shfl_xor_sync(0xffffffffu, ix, o);
            float nm = fminf(m, om);
            s = s * __expf(nm - m) + os * __expf(nm - om);
            if (om < m || (om == m && oi < ix)) ix = oi;
            m = nm;
        }
        if (lc == 0) {
            const int rowl = wm * 32 + (i >> 1) * 16 + lr + (i & 1) * 8;
            rm[rowl * 4 + wn] = m;
            rs[rowl * 4 + wn] = s;
            ri[rowl * 4 + wn] = ix;
        }
    }
    __syncthreads();
    if (tid < TM) {
        float m = rm[tid * 4], s = rs[tid * 4];
        int   ix = ri[tid * 4];
        #pragma unroll
        for (int w = 1; w < 4; w++) {
            float om = rm[tid * 4 + w], os = rs[tid * 4 + w];
            int   oi = ri[tid * 4 + w];
            float nm = fminf(m, om);
            s = s * __expf(nm - m) + os * __expf(nm - om);
            if (om < m || (om == m && oi < ix)) ix = oi;
            m = nm;
        }
        g_pm[nseg][m0 + tid] = m;
        g_ps[nseg][m0 + tid] = s;
        g_pi[nseg][m0 + tid] = ix;
    }
}

// ---------------- merge the 4 N-segment partials per row ----------------
__global__ void merge_kernel() {
    int i = blockIdx.x * blockDim.x + threadIdx.x;
    if (i >= N_INPUTS) return;
    float m = g_pm[0][i], s = g_ps[0][i];
    int   ix = g_pi[0][i];
    #pragma unroll
    for (int seg = 1; seg < NSEG; seg++) {
        float om = g_pm[seg][i], os = g_ps[seg][i];
        int   oi = g_pi[seg][i];
        float nm = fminf(m, om);
        s = s * __expf(nm - m) + os * __expf(nm - om);
        if (om < m) ix = oi;            // ties keep earlier segment (lower index)
        m = nm;
    }
    g_minv[i]   = m;
    g_rsum[i]   = 1.0f / s;
    g_argmin[i] = ix;
}

// ---------------- quantized_st + histogram + mse ----------------
__global__ void quantize_kernel(const float* __restrict__ X, const float* __restrict__ W,
                                float* __restrict__ qout) {
    int warp = (blockIdx.x * blockDim.x + threadIdx.x) >> 5;
    int lane = threadIdx.x & 31;
    if (warp >= N_INPUTS) return;
    const int idx = g_argmin[warp];
    if (lane == 0) atomicAdd(&g_counts[idx], 1);

    const float4* xp = (const float4*)(X + (size_t)warp * DIM);
    const float4* wp = (const float4*)(W + (size_t)idx * DIM);
    float4*       qp = (float4*)(qout + (size_t)warp * DIM);
    float sq = 0.f;
    #pragma unroll
    for (int i = lane; i < DIM / 4; i += 32) {
        float4 xv = xp[i], wv = wp[i];
        float tx = wv.x - xv.x, ty = wv.y - xv.y, tz = wv.z - xv.z, tw = wv.w - xv.w;
        qp[i] = wv;
        sq += tx * tx + ty * ty + tz * tz + tw * tw;
    }
    #pragma unroll
    for (int o = 16; o; o >>= 1) sq += __shfl_xor_sync(0xffffffffu, sq, o);
    if (lane == 0) atomicAdd(&g_mse, (double)sq);
}

// ---------------- normalize distances -> probs (streaming hints only) ----------------
__global__ void norm_probs_kernel(float* __restrict__ probs) {
    const size_t i4 = (size_t)blockIdx.x * blockDim.x + threadIdx.x;
    const int row = (int)(i4 >> 11);          // 2048 float4 per row
    const float m  = g_minv[row];
    const float rs = g_rsum[row];
    float4 v = __ldcs((const float4*)probs + i4);
    v.x = __expf(m - v.x) * rs;
    v.y = __expf(m - v.y) * rs;
    v.z = __expf(m - v.z) * rs;
    v.w = __expf(m - v.w) * rs;
    __stcs((float4*)probs + i4, v);
}

// ---------------- loss + perplexity ----------------
__global__ void finalize_kernel(float* __restrict__ out_loss, float* __restrict__ out_perp) {
    __shared__ double sh[256];
    const int tid = threadIdx.x;
    double h = 0.0;
    for (int i = tid; i < N_CODES; i += 256) {
        float avg = (float)g_counts[i] / (float)N_INPUTS;
        h -= (double)(avg * logf(avg + 1e-10f));
    }
    sh[tid] = h;
    __syncthreads();
    for (int o = 128; o; o >>= 1) {
        if (tid < o) sh[tid] += sh[tid + o];
        __syncthreads();
    }
    if (tid == 0) {
        *out_perp = expf((float)sh[0]);
        *out_loss = (float)(1.25 * g_mse / (double)((size_t)N_INPUTS * DIM));
    }
}

// ---------------- launch ----------------
extern "C" void kernel_launch(void* const* d_in, const int* in_sizes, int n_in,
                              void* d_out, int out_size) {
    const float* X = (const float*)d_in[0];
    const float* W = (const float*)d_in[1];
    float* out = (float*)d_out;

    float* q_out    = out;
    float* probs    = out + (size_t)N_INPUTS * DIM;
    float* loss_out = probs + (size_t)N_INPUTS * N_CODES;
    float* perp_out = loss_out + 1;

    init_kernel<<<(N_CODES + 255) / 256, 256>>>();

    const size_t ngroups = (size_t)N_INPUTS * 64 + (size_t)N_CODES * 64;
    convert_kernel<<<(unsigned)((ngroups + 255) / 256), 256>>>(X, W);

    float* d_xnorm; cudaGetSymbolAddress((void**)&d_xnorm, g_xnorm);
    float* d_wnorm; cudaGetSymbolAddress((void**)&d_wnorm, g_wnorm);
    row_norm_kernel<<<(N_INPUTS * 32) / 256, 256>>>(X, d_xnorm, N_INPUTS);
    row_norm_kernel<<<(N_CODES  * 32) / 256, 256>>>(W, d_wnorm, N_CODES);

    cudaFuncSetAttribute(dist_kernel, cudaFuncAttributeMaxDynamicSharedMemorySize, SMEM_TOTAL);
    dist_kernel<<<NBLK * NSEG, NTHREADS, SMEM_TOTAL>>>(probs);

    merge_kernel<<<N_INPUTS / 256, 256>>>();

    quantize_kernel<<<(N_INPUTS * 32) / 256, 256>>>(X, W, q_out);

    const size_t n4 = (size_t)N_INPUTS * N_CODES / 4;
    norm_probs_kernel<<<(unsigned)(n4 / 256), 256>>>(probs);

    finalize_kernel<<<1, 256>>>(loss_out, perp_out);
}

// round 17
// speedup vs baseline: 1.4578x; 1.0078x over previous
#include <cuda_runtime.h>
#include <cuda_fp16.h>
#include <math.h>
#include <stdint.h>

#define N_INPUTS   32768
#define N_CODES    8192
#define DIM        512

#define TM       128
#define TN       128
#define KC       64
#define NSEG     4                    // N split into 4 segments of 2048
#define NT_SEG   16                   // N-tiles per segment
#define TOTAL    (NT_SEG * 8)         // 128 chunks per job
#define NTHREADS 512
#define NBLK     (N_INPUTS / TM)      // 256 row-blocks
#define CHUNK_HALFS 8192              // 128 rows x 64 cols
#define CHUNK_BYTES 16384

// ---------------- device scratch (tiled + swizzled layouts) ----------------
__device__ __half g_xhi[(size_t)N_INPUTS * DIM];
__device__ __half g_xlo[(size_t)N_INPUTS * DIM];
__device__ __half g_whi[(size_t)N_CODES * DIM];
__device__ __half g_wlo[(size_t)N_CODES * DIM];
__device__ float  g_xnorm[N_INPUTS];
__device__ float  g_wnorm[N_CODES];
__device__ float  g_pm[NSEG][N_INPUTS];
__device__ float  g_ps[NSEG][N_INPUTS];
__device__ int    g_pi[NSEG][N_INPUTS];
__device__ float  g_minv[N_INPUTS];
__device__ float  g_rsum[N_INPUTS];
__device__ int    g_argmin[N_INPUTS];
__device__ int    g_counts[N_CODES];
__device__ double g_mse;

// ---------------- SMEM layout (bytes) ----------------
#define OFF_AH   0
#define OFF_AL   16384
#define OFF_BH   32768
#define OFF_BL   49152
#define STAGE_SZ 65536
#define OFF_RM   131072      // float[128][4]
#define OFF_RS   133120      // float[128][4]
#define OFF_RI   135168      // int  [128][4]
#define OFF_BAR  137216      // 2 mbarriers
#define SMEM_TOTAL 137344

// ---------------- helpers ----------------
__device__ __forceinline__ uint32_t smem_u32(const void* p) {
    uint32_t a;
    asm("{ .reg .u64 t; cvta.to.shared.u64 t, %1; cvt.u32.u64 %0, t; }" : "=r"(a) : "l"(p));
    return a;
}
__device__ __forceinline__ void ldsm4(uint32_t* r, uint32_t a) {
    asm volatile("ldmatrix.sync.aligned.m8n8.x4.shared.b16 {%0,%1,%2,%3}, [%4];"
                 : "=r"(r[0]), "=r"(r[1]), "=r"(r[2]), "=r"(r[3]) : "r"(a));
}
__device__ __forceinline__ void mma16816(float* c, const uint32_t* a, uint32_t b0, uint32_t b1) {
    asm volatile("mma.sync.aligned.m16n8k16.row.col.f32.f16.f16.f32 "
                 "{%0,%1,%2,%3}, {%4,%5,%6,%7}, {%8,%9}, {%0,%1,%2,%3};"
                 : "+f"(c[0]), "+f"(c[1]), "+f"(c[2]), "+f"(c[3])
                 : "r"(a[0]), "r"(a[1]), "r"(a[2]), "r"(a[3]), "r"(b0), "r"(b1));
}
// fp16-accumulate variant (2x rate): c = 2 b32 regs holding {c0,c1},{c2,c3} halves
__device__ __forceinline__ void mma16816_h(uint32_t* c, const uint32_t* a, uint32_t b0, uint32_t b1) {
    asm volatile("mma.sync.aligned.m16n8k16.row.col.f16.f16.f16.f16 "
                 "{%0,%1}, {%2,%3,%4,%5}, {%6,%7}, {%0,%1};"
                 : "+r"(c[0]), "+r"(c[1])
                 : "r"(a[0]), "r"(a[1]), "r"(a[2]), "r"(a[3]), "r"(b0), "r"(b1));
}
__device__ __forceinline__ void mbar_init(uint32_t mbar, uint32_t count) {
    asm volatile("mbarrier.init.shared.b64 [%0], %1;" :: "r"(mbar), "r"(count) : "memory");
}
__device__ __forceinline__ void mbar_expect(uint32_t mbar, uint32_t tx) {
    asm volatile("mbarrier.arrive.expect_tx.shared.b64 _, [%0], %1;" :: "r"(mbar), "r"(tx) : "memory");
}
__device__ __forceinline__ void mbar_wait(uint32_t mbar, uint32_t parity) {
    asm volatile(
        "{\n\t.reg .pred P;\n\t"
        "WL_%=:\n\t"
        "mbarrier.try_wait.parity.acquire.cta.shared::cta.b64 P, [%0], %1, 0x989680;\n\t"
        "@P bra.uni WD_%=;\n\t"
        "bra.uni WL_%=;\n\t"
        "WD_%=:\n\t}"
        :: "r"(mbar), "r"(parity) : "memory");
}
__device__ __forceinline__ void bulk_cp(uint32_t dst, const void* src, uint32_t bytes, uint32_t mbar) {
    asm volatile("cp.async.bulk.shared::cluster.global.mbarrier::complete_tx::bytes [%0], [%1], %2, [%3];"
                 :: "r"(dst), "l"(__cvta_generic_to_global(src)), "r"(bytes), "r"(mbar) : "memory");
}

// ---------------- small kernels ----------------
__global__ void init_kernel() {
    int i = blockIdx.x * blockDim.x + threadIdx.x;
    if (i < N_CODES) g_counts[i] = 0;
    if (i == 0) g_mse = 0.0;
}

// convert fp32 -> split fp16 hi/lo, writing the tiled+swizzled chunk layout
__global__ void convert_kernel(const float* __restrict__ X, const float* __restrict__ W) {
    const size_t NXG = (size_t)N_INPUTS * 64;   // 16B-groups in X
    const size_t NWG = (size_t)N_CODES * 64;
    size_t idx = (size_t)blockIdx.x * blockDim.x + threadIdx.x;
    if (idx >= NXG + NWG) return;
    const float* src; __half *hdst, *ldst; size_t r; int g;
    if (idx < NXG) { src = X; hdst = g_xhi; ldst = g_xlo; r = idx >> 6; g = (int)(idx & 63); }
    else { idx -= NXG; src = W; hdst = g_whi; ldst = g_wlo; r = idx >> 6; g = (int)(idx & 63); }

    float4 v0 = *(const float4*)(src + r * DIM + g * 8);
    float4 v1 = *(const float4*)(src + r * DIM + g * 8 + 4);
    __half h[8], l[8];
    float f[8] = {v0.x, v0.y, v0.z, v0.w, v1.x, v1.y, v1.z, v1.w};
    #pragma unroll
    for (int i = 0; i < 8; i++) {
        h[i] = __float2half(f[i]);
        l[i] = __float2half(f[i] - __half2float(h[i]));
    }
    const int rb = (int)(r >> 7), rl = (int)(r & 127);
    const int kc = g >> 3, gin = g & 7;
    const size_t dst = ((size_t)(rb * 8 + kc) * 128 + rl) * 64 + (size_t)((gin ^ (rl & 7)) * 8);
    *(uint4*)(hdst + dst) = *(uint4*)h;
    *(uint4*)(ldst + dst) = *(uint4*)l;
}

__global__ void row_norm_kernel(const float* __restrict__ src, float* __restrict__ dst, int rows) {
    int warp = (blockIdx.x * blockDim.x + threadIdx.x) >> 5;
    int lane = threadIdx.x & 31;
    if (warp >= rows) return;
    const float4* p = (const float4*)(src + (size_t)warp * DIM);
    float s = 0.f;
    #pragma unroll
    for (int i = lane; i < DIM / 4; i += 32) {
        float4 v = p[i];
        s += v.x * v.x + v.y * v.y + v.z * v.z + v.w * v.w;
    }
    #pragma unroll
    for (int o = 16; o; o >>= 1) s += __shfl_xor_sync(0xffffffffu, s, o);
    if (lane == 0) dst[warp] = s;
}

// ---------------- main HMMA distance kernel (1024 jobs: 256 rowblocks x 4 N-segments) ----------------
__global__ void __launch_bounds__(NTHREADS, 1)
dist_kernel(float* __restrict__ probs) {
    extern __shared__ __align__(1024) char smem[];
    const int tid  = threadIdx.x;
    const int mb   = blockIdx.x & (NBLK - 1);      // row-block
    const int nseg = blockIdx.x >> 8;              // N segment (0..3)
    const int m0   = mb * TM;
    const int tbase = nseg * NT_SEG;               // absolute first N-tile
    const int warp = tid >> 5, lane = tid & 31;
    const int wm = warp >> 2, wn = warp & 3;       // 4 x 4 warp grid, 32x32 warp tiles
    const int lr = lane >> 2, lc = lane & 3;
    const uint32_t sbase = smem_u32(smem);
    const uint32_t bar0 = sbase + OFF_BAR, bar1 = sbase + OFF_BAR + 8;

    if (tid == 0) { mbar_init(bar0, 1); mbar_init(bar1, 1); }
    __syncthreads();

    // ---- ldmatrix per-thread constants ----
    const uint32_t aofs = (uint32_t)((wm * 32 + (lane & 15)) << 7);
    const uint32_t bofs = (uint32_t)((wn * 32 + (lane & 15)) << 7);
    const int gsel = lane >> 4, gsw = lane & 7;

    float acc[2][4][4];           // fp32 accumulators: xh*wh
    uint32_t accC[2][4][2];       // fp16 accumulators: xh*wl + xl*wh
    #pragma unroll
    for (int a = 0; a < 2; a++)
        #pragma unroll
        for (int b = 0; b < 4; b++) {
            #pragma unroll
            for (int c = 0; c < 4; c++) acc[a][b][c] = 0.f;
            accC[a][b][0] = 0u; accC[a][b][1] = 0u;
        }

    float stm[4], sts[4];
    int   sti[4];
    float xnr[4];
    #pragma unroll
    for (int i = 0; i < 4; i++) {
        stm[i] = 3.0e38f; sts[i] = 0.f; sti[i] = 0;
        xnr[i] = g_xnorm[m0 + wm * 32 + (i >> 1) * 16 + lr + (i & 1) * 8];
    }

    // ---- prologue: bulk-load chunk 0 into stage 0 ----
    if (tid == 0) {
        const size_t ac = (size_t)(mb * 8 + 0) * CHUNK_HALFS;
        const size_t bc = (size_t)(tbase * 8 + 0) * CHUNK_HALFS;
        mbar_expect(bar0, 4 * CHUNK_BYTES);
        bulk_cp(sbase + OFF_AH, g_xhi + ac, CHUNK_BYTES, bar0);
        bulk_cp(sbase + OFF_AL, g_xlo + ac, CHUNK_BYTES, bar0);
        bulk_cp(sbase + OFF_BH, g_whi + bc, CHUNK_BYTES, bar0);
        bulk_cp(sbase + OFF_BL, g_wlo + bc, CHUNK_BYTES, bar0);
    }

    for (int g = 0; g < TOTAL; g++) {
        // ---- issue bulk loads for chunk g+1 ----
        if (g + 1 < TOTAL && tid == 0) {
            const int kc1 = (g + 1) & 7, nt1 = (g + 1) >> 3;
            const uint32_t st = sbase + (uint32_t)((g + 1) & 1) * STAGE_SZ;
            const uint32_t bar = ((g + 1) & 1) ? bar1 : bar0;
            const size_t ac = (size_t)(mb * 8 + kc1) * CHUNK_HALFS;
            const size_t bc = (size_t)((tbase + nt1) * 8 + kc1) * CHUNK_HALFS;
            mbar_expect(bar, 4 * CHUNK_BYTES);
            bulk_cp(st + OFF_AH, g_xhi + ac, CHUNK_BYTES, bar);
            bulk_cp(st + OFF_AL, g_xlo + ac, CHUNK_BYTES, bar);
            bulk_cp(st + OFF_BH, g_whi + bc, CHUNK_BYTES, bar);
            bulk_cp(st + OFF_BL, g_wlo + bc, CHUNK_BYTES, bar);
        }
        mbar_wait((g & 1) ? bar1 : bar0, (g >> 1) & 1);

        // ---- compute chunk g ----
        {
            const uint32_t st = sbase + (uint32_t)(g & 1) * STAGE_SZ;
            #pragma unroll
            for (int ks = 0; ks < 4; ks++) {
                const uint32_t gx = (uint32_t)((((ks << 1) | gsel) ^ gsw) << 4);
                uint32_t ah[2][4], bh[2][4], bl[2][4], al[2][4];
                #pragma unroll
                for (int mbk = 0; mbk < 2; mbk++) ldsm4(ah[mbk], st + OFF_AH + aofs + mbk * 2048 + gx);
                #pragma unroll
                for (int nb = 0; nb < 2; nb++) ldsm4(bh[nb], st + OFF_BH + bofs + nb * 2048 + gx);
                // main product: fp32 accumulate
                #pragma unroll
                for (int mbk = 0; mbk < 2; mbk++)
                    #pragma unroll
                    for (int n8 = 0; n8 < 4; n8++)
                        mma16816(acc[mbk][n8], ah[mbk], bh[n8 >> 1][n8 & 1], bh[n8 >> 1][(n8 & 1) + 2]);
                // corrections: fp16 accumulate (2x rate)
                #pragma unroll
                for (int nb = 0; nb < 2; nb++) ldsm4(bl[nb], st + OFF_BL + bofs + nb * 2048 + gx);
                #pragma unroll
                for (int mbk = 0; mbk < 2; mbk++)
                    #pragma unroll
                    for (int n8 = 0; n8 < 4; n8++)
                        mma16816_h(accC[mbk][n8], ah[mbk], bl[n8 >> 1][n8 & 1], bl[n8 >> 1][(n8 & 1) + 2]);
                #pragma unroll
                for (int mbk = 0; mbk < 2; mbk++) ldsm4(al[mbk], st + OFF_AL + aofs + mbk * 2048 + gx);
                #pragma unroll
                for (int mbk = 0; mbk < 2; mbk++)
                    #pragma unroll
                    for (int n8 = 0; n8 < 4; n8++)
                        mma16816_h(accC[mbk][n8], al[mbk], bh[n8 >> 1][n8 & 1], bh[n8 >> 1][(n8 & 1) + 2]);
            }
        }

        // ---- epilogue at end of each N-tile ----
        if ((g & 7) == 7) {
            const int n0 = (tbase + (g >> 3)) * TN;
            float wns[8];
            #pragma unroll
            for (int nb = 0; nb < 4; nb++) {
                wns[nb * 2]     = __ldg(&g_wnorm[n0 + wn * 32 + nb * 8 + lc * 2]);
                wns[nb * 2 + 1] = __ldg(&g_wnorm[n0 + wn * 32 + nb * 8 + lc * 2 + 1]);
            }
            #pragma unroll
            for (int mbk = 0; mbk < 2; mbk++)
                #pragma unroll
                for (int h = 0; h < 2; h++) {
                    const int i = mbk * 2 + h;
                    const int grow = m0 + wm * 32 + mbk * 16 + lr + h * 8;
                    #pragma unroll
                    for (int nb = 0; nb < 4; nb++) {
                        const int col = n0 + wn * 32 + nb * 8 + lc * 2;
                        // unpack fp16 correction pair for this h-group
                        float2 fc = __half22float2(*(__half2*)&accC[mbk][nb][h]);
                        float dot0 = acc[mbk][nb][h * 2]     + fc.x;
                        float dot1 = acc[mbk][nb][h * 2 + 1] + fc.y;
                        float d0 = fmaf(-2.f, dot0, xnr[i] + wns[nb * 2]);
                        float d1 = fmaf(-2.f, dot1, xnr[i] + wns[nb * 2 + 1]);
                        *(float2*)(probs + (size_t)grow * N_CODES + col) = make_float2(d0, d1);
                        if (d0 < stm[i]) { sts[i] = fmaf(sts[i], __expf(d0 - stm[i]), 1.0f); stm[i] = d0; sti[i] = col; }
                        else               sts[i] += __expf(stm[i] - d0);
                        if (d1 < stm[i]) { sts[i] = fmaf(sts[i], __expf(d1 - stm[i]), 1.0f); stm[i] = d1; sti[i] = col + 1; }
                        else               sts[i] += __expf(stm[i] - d1);
                        acc[mbk][nb][h * 2] = 0.f; acc[mbk][nb][h * 2 + 1] = 0.f;
                        accC[mbk][nb][h] = 0u;
                    }
                }
        }
        __syncthreads();
    }

    // ---- final merge: quad lanes -> smem -> per-row over 4 N-warps ----
    float* rm = (float*)(smem + OFF_RM);
    float* rs = (float*)(smem + OFF_RS);
    int*   ri = (int*)  (smem + OFF_RI);
    #pragma unroll
    for (int i = 0; i < 4; i++) {
        float m = stm[i], s = sts[i];
        int   ix = sti[i];
        #pragma unroll
        for (int o = 1; o <= 2; o <<= 1) {
            float om = __shfl_xor_sync(0xffffffffu, m, o);
            float os = __shfl_xor_sync(0xffffffffu, s, o);
            int   oi = __shfl_xor_sync(0xffffffffu, ix, o);
            float nm = fminf(m, om);
            s = s * __expf(nm - m) + os * __expf(nm - om);
            if (om < m || (om == m && oi < ix)) ix = oi;
            m = nm;
        }
        if (lc == 0) {
            const int rowl = wm * 32 + (i >> 1) * 16 + lr + (i & 1) * 8;
            rm[rowl * 4 + wn] = m;
            rs[rowl * 4 + wn] = s;
            ri[rowl * 4 + wn] = ix;
        }
    }
    __syncthreads();
    if (tid < TM) {
        float m = rm[tid * 4], s = rs[tid * 4];
        int   ix = ri[tid * 4];
        #pragma unroll
        for (int w = 1; w < 4; w++) {
            float om = rm[tid * 4 + w], os = rs[tid * 4 + w];
            int   oi = ri[tid * 4 + w];
            float nm = fminf(m, om);
            s = s * __expf(nm - m) + os * __expf(nm - om);
            if (om < m || (om == m && oi < ix)) ix = oi;
            m = nm;
        }
        g_pm[nseg][m0 + tid] = m;
        g_ps[nseg][m0 + tid] = s;
        g_pi[nseg][m0 + tid] = ix;
    }
}

// ---------------- merge the 4 N-segment partials per row ----------------
__global__ void merge_kernel() {
    int i = blockIdx.x * blockDim.x + threadIdx.x;
    if (i >= N_INPUTS) return;
    float m = g_pm[0][i], s = g_ps[0][i];
    int   ix = g_pi[0][i];
    #pragma unroll
    for (int seg = 1; seg < NSEG; seg++) {
        float om = g_pm[seg][i], os = g_ps[seg][i];
        int   oi = g_pi[seg][i];
        float nm = fminf(m, om);
        s = s * __expf(nm - m) + os * __expf(nm - om);
        if (om < m) ix = oi;            // ties keep earlier segment (lower index)
        m = nm;
    }
    g_minv[i]   = m;
    g_rsum[i]   = 1.0f / s;
    g_argmin[i] = ix;
}

// ---------------- quantized_st + histogram + mse ----------------
__global__ void quantize_kernel(const float* __restrict__ X, const float* __restrict__ W,
                                float* __restrict__ qout) {
    int warp = (blockIdx.x * blockDim.x + threadIdx.x) >> 5;
    int lane = threadIdx.x & 31;
    if (warp >= N_INPUTS) return;
    const int idx = g_argmin[warp];
    if (lane == 0) atomicAdd(&g_counts[idx], 1);

    const float4* xp = (const float4*)(X + (size_t)warp * DIM);
    const float4* wp = (const float4*)(W + (size_t)idx * DIM);
    float4*       qp = (float4*)(qout + (size_t)warp * DIM);
    float sq = 0.f;
    #pragma unroll
    for (int i = lane; i < DIM / 4; i += 32) {
        float4 xv = xp[i], wv = wp[i];
        float tx = wv.x - xv.x, ty = wv.y - xv.y, tz = wv.z - xv.z, tw = wv.w - xv.w;
        qp[i] = wv;
        sq += tx * tx + ty * ty + tz * tz + tw * tw;
    }
    #pragma unroll
    for (int o = 16; o; o >>= 1) sq += __shfl_xor_sync(0xffffffffu, sq, o);
    if (lane == 0) atomicAdd(&g_mse, (double)sq);
}

// ---------------- normalize distances -> probs ----------------
__global__ void norm_probs_kernel(float* __restrict__ probs) {
    const size_t i4 = (size_t)blockIdx.x * blockDim.x + threadIdx.x;
    const int row = (int)(i4 >> 11);          // 2048 float4 per row
    const float m  = g_minv[row];
    const float rs = g_rsum[row];
    float4 v = __ldcs((const float4*)probs + i4);
    v.x = __expf(m - v.x) * rs;
    v.y = __expf(m - v.y) * rs;
    v.z = __expf(m - v.z) * rs;
    v.w = __expf(m - v.w) * rs;
    __stcs((float4*)probs + i4, v);
}

// ---------------- loss + perplexity ----------------
__global__ void finalize_kernel(float* __restrict__ out_loss, float* __restrict__ out_perp) {
    __shared__ double sh[256];
    const int tid = threadIdx.x;
    double h = 0.0;
    for (int i = tid; i < N_CODES; i += 256) {
        float avg = (float)g_counts[i] / (float)N_INPUTS;
        h -= (double)(avg * logf(avg + 1e-10f));
    }
    sh[tid] = h;
    __syncthreads();
    for (int o = 128; o; o >>= 1) {
        if (tid < o) sh[tid] += sh[tid + o];
        __syncthreads();
    }
    if (tid == 0) {
        *out_perp = expf((float)sh[0]);
        *out_loss = (float)(1.25 * g_mse / (double)((size_t)N_INPUTS * DIM));
    }
}

// ---------------- launch ----------------
extern "C" void kernel_launch(void* const* d_in, const int* in_sizes, int n_in,
                              void* d_out, int out_size) {
    const float* X = (const float*)d_in[0];
    const float* W = (const float*)d_in[1];
    float* out = (float*)d_out;

    float* q_out    = out;
    float* probs    = out + (size_t)N_INPUTS * DIM;
    float* loss_out = probs + (size_t)N_INPUTS * N_CODES;
    float* perp_out = loss_out + 1;

    init_kernel<<<(N_CODES + 255) / 256, 256>>>();

    const size_t ngroups = (size_t)N_INPUTS * 64 + (size_t)N_CODES * 64;
    convert_kernel<<<(unsigned)((ngroups + 255) / 256), 256>>>(X, W);

    float* d_xnorm; cudaGetSymbolAddress((void**)&d_xnorm, g_xnorm);
    float* d_wnorm; cudaGetSymbolAddress((void**)&d_wnorm, g_wnorm);
    row_norm_kernel<<<(N_INPUTS * 32) / 256, 256>>>(X, d_xnorm, N_INPUTS);
    row_norm_kernel<<<(N_CODES  * 32) / 256, 256>>>(W, d_wnorm, N_CODES);

    cudaFuncSetAttribute(dist_kernel, cudaFuncAttributeMaxDynamicSharedMemorySize, SMEM_TOTAL);
    dist_kernel<<<NBLK * NSEG, NTHREADS, SMEM_TOTAL>>>(probs);

    merge_kernel<<<N_INPUTS / 256, 256>>>();

    quantize_kernel<<<(N_INPUTS * 32) / 256, 256>>>(X, W, q_out);

    const size_t n4 = (size_t)N_INPUTS * N_CODES / 4;
    norm_probs_kernel<<<(unsigned)(n4 / 256), 256>>>(probs);

    finalize_kernel<<<1, 256>>>(loss_out, perp_out);
}